// round 7
// baseline (speedup 1.0000x reference)
#include <cuda_runtime.h>
#include <math.h>

#define T_STEPS 1000
#define BATCH   1024
#define IN_DIM  80
#define HID     128
#define OUT_DIM 10

#define N_CONS   128                 // consumer slots (8 batch each, 1 per SM)
#define N_CTAS   296                 // 148 SMs * 2 — single wave guaranteed
#define TILE_R   64                  // rows per producer tile
#define N_TILES  ((T_STEPS * BATCH) / TILE_R)   // 16000
#define TILES_PER_T (BATCH / TILE_R)            // 16

typedef unsigned long long ull;

__device__ float g_xw[(size_t)T_STEPS * BATCH * HID];   // 512 MB scratch
__device__ float g_w_inT[IN_DIM * HID];                 // w_inT[k*128+h] = w_in[h*80+k]
__device__ volatile unsigned g_cnt[T_STEPS];            // tiles completed per t-chunk
__device__ unsigned g_role[160];                        // per-SM ticket
__device__ unsigned g_cons_ctr;                         // consumer id allocator
__device__ unsigned g_tile_ctr;                         // producer tile queue

__device__ __forceinline__ ull pk2(float lo, float hi) {
    ull r; asm("mov.b64 %0, {%1, %2};" : "=l"(r) : "f"(lo), "f"(hi)); return r;
}
__device__ __forceinline__ ull ffma2(ull a, ull b, ull c) {
    ull d; asm("fma.rn.f32x2 %0, %1, %2, %3;" : "=l"(d) : "l"(a), "l"(b), "l"(c)); return d;
}

// ---------------------------------------------------------------------------
// Init: transpose w_in, zero all counters (runs every launch — graph-safe)
// ---------------------------------------------------------------------------
__global__ void init_kernel(const float* __restrict__ w_in, float* __restrict__ w_inT) {
    int idx = blockIdx.x * 256 + threadIdx.x;
    if (idx < IN_DIM * HID) {
        int k = idx >> 7, h = idx & 127;
        w_inT[idx] = w_in[h * IN_DIM + k];
    }
    if (idx < T_STEPS) g_cnt[idx] = 0u;
    if (idx < 160) g_role[idx] = 0u;
    if (idx == 0) { g_cons_ctr = 0u; g_tile_ctr = 0u; }
}

__device__ __forceinline__ void wait_chunk(int t) {
    if (g_cnt[t] < TILES_PER_T) {
        while (g_cnt[t] < TILES_PER_T) __nanosleep(64);
    }
    __threadfence();   // acquire
}

// ---------------------------------------------------------------------------
// Fused persistent kernel, SM-aware roles: exactly 1 consumer CTA per SM on
// 128 SMs; remaining 168 CTAs are GEMM producers (atomic tile queue).
// ---------------------------------------------------------------------------
__global__ void __launch_bounds__(256, 2) snn_fused_kernel(
        const float* __restrict__ x,
        const float* __restrict__ w_inT,
        const float* __restrict__ w_rec,
        const float* __restrict__ w_out,
        float* __restrict__ xw,
        float* __restrict__ out) {
    extern __shared__ float smem[];
    __shared__ int s_role, s_id;
    __shared__ unsigned s_tile;
    int tid = threadIdx.x;

    if (tid == 0) {
        unsigned smid; asm("mov.u32 %0, %%smid;" : "=r"(smid));
        int role = 1, id = -1;
        if (atomicAdd(&g_role[smid], 1u) == 0u) {
            unsigned c = atomicAdd(&g_cons_ctr, 1u);
            if (c < N_CONS) { role = 0; id = (int)c; }
        }
        s_role = role; s_id = id;
    }
    __syncthreads();

    if (s_role == 1) {
        // =================== PRODUCER: xw = x @ w_in.T ====================
        // Bitwise chain == R4: ascending k, single acc, fma.rn.f32x2 h-pairs.
        float* xs = smem;                 // [64][81] padded
        float* ws = smem + TILE_R * 81;   // [80][128]

        for (int idx = tid; idx < IN_DIM * HID; idx += 256)
            ws[idx] = w_inT[idx];

        int hg = tid & 15;    // h pairs 2hg + 32j, j<4
        int rg = tid >> 4;    // rows rg + 16i,  i<4

        for (;;) {
            if (tid == 0) s_tile = atomicAdd(&g_tile_ctr, 1u);
            __syncthreads();
            unsigned tile = s_tile;
            if (tile >= N_TILES) break;

            long row0 = (long)tile * TILE_R;
            const float* xsrc = x + row0 * IN_DIM;
            for (int idx = tid; idx < TILE_R * IN_DIM; idx += 256) {
                int r = idx / IN_DIM, k = idx - r * IN_DIM;
                xs[r * 81 + k] = xsrc[idx];
            }
            __syncthreads();

            ull acc[4][4];
#pragma unroll
            for (int i = 0; i < 4; ++i)
#pragma unroll
                for (int j = 0; j < 4; ++j) acc[i][j] = 0ull;

#pragma unroll 10
            for (int k = 0; k < IN_DIM; ++k) {
                ull wp[4];
#pragma unroll
                for (int j = 0; j < 4; ++j)
                    wp[j] = *(const ull*)&ws[k * HID + 2 * hg + 32 * j];
                float xv[4];
#pragma unroll
                for (int i = 0; i < 4; ++i)
                    xv[i] = xs[(rg + 16 * i) * 81 + k];
#pragma unroll
                for (int i = 0; i < 4; ++i) {
                    ull xd = pk2(xv[i], xv[i]);
#pragma unroll
                    for (int j = 0; j < 4; ++j)
                        acc[i][j] = ffma2(xd, wp[j], acc[i][j]);
                }
            }

#pragma unroll
            for (int i = 0; i < 4; ++i) {
                float* dst = &xw[(row0 + rg + 16 * i) * HID];
#pragma unroll
                for (int j = 0; j < 4; ++j)
                    *(ull*)&dst[2 * hg + 32 * j] = acc[i][j];
            }

            __threadfence();      // release: tile stores visible before bump
            __syncthreads();      // also protects xs/s_tile for next iteration
            if (tid == 0)
                atomicAdd((unsigned*)&g_cnt[tile / TILES_PER_T], 1u);
        }
        return;
    }

    // ===================== CONSUMER: sequential recurrence ====================
    float* wr_p = smem;              // [128][128] permuted: wr_p[j*128+4*(h&31)+(h>>5)]
    float* wo_s = smem + HID * HID;  // [128][16]

    for (int idx = tid; idx < HID * HID; idx += 256) {
        int h = idx >> 7, j = idx & 127;
        wr_p[(j << 7) + ((h & 31) << 2) + (h >> 5)] = w_rec[idx];
    }
    for (int idx = tid; idx < HID * 16; idx += 256) {
        int j = idx >> 4, o = idx & 15;
        wo_s[idx] = (o < OUT_DIM) ? w_out[o * HID + j] : 0.0f;
    }
    __syncthreads();

    int warp = tid >> 5, lane = tid & 31;
    int batch = s_id * 8 + warp;

    float v0 = 0.f, v1 = 0.f, v2 = 0.f, v3 = 0.f;
    float c0 = 0.f, c1 = 0.f, c2 = 0.f, c3 = 0.f;
    float vo = 0.f, io = 0.f;

    const float* xwp = xw + (size_t)batch * HID + lane;

    // prefetch pipeline, distance 2
    wait_chunk(0);
    float x0 = xwp[0], x1 = xwp[32], x2 = xwp[64], x3 = xwp[96];
    wait_chunk(1);
    const float* p1 = xwp + (size_t)(BATCH * HID);
    float a0 = p1[0], a1 = p1[32], a2 = p1[64], a3 = p1[96];

    for (int t = 0; t < T_STEPS; ++t) {
        // --- LIF (exact reference order, separate rounding) ---
        float vd0 = __fadd_rn(v0, __fmul_rn(0.1f, __fadd_rn(__fsub_rn(0.f, v0), c0)));
        float vd1 = __fadd_rn(v1, __fmul_rn(0.1f, __fadd_rn(__fsub_rn(0.f, v1), c1)));
        float vd2 = __fadd_rn(v2, __fmul_rn(0.1f, __fadd_rn(__fsub_rn(0.f, v2), c2)));
        float vd3 = __fadd_rn(v3, __fmul_rn(0.1f, __fadd_rn(__fsub_rn(0.f, v3), c3)));
        float id0 = __fsub_rn(c0, __fmul_rn(0.2f, c0));
        float id1 = __fsub_rn(c1, __fmul_rn(0.2f, c1));
        float id2 = __fsub_rn(c2, __fmul_rn(0.2f, c2));
        float id3 = __fsub_rn(c3, __fmul_rn(0.2f, c3));
        bool z0 = __fsub_rn(vd0, 1.0f) > 0.0f;
        bool z1 = __fsub_rn(vd1, 1.0f) > 0.0f;
        bool z2 = __fsub_rn(vd2, 1.0f) > 0.0f;
        bool z3 = __fsub_rn(vd3, 1.0f) > 0.0f;
        v0 = z0 ? 0.f : vd0;
        v1 = z1 ? 0.f : vd1;
        v2 = z2 ? 0.f : vd2;
        v3 = z3 ? 0.f : vd3;

        unsigned m0 = __ballot_sync(0xffffffffu, z0);
        unsigned m1 = __ballot_sync(0xffffffffu, z1);
        unsigned m2 = __ballot_sync(0xffffffffu, z2);
        unsigned m3 = __ballot_sync(0xffffffffu, z3);

        // prefetch xw[t+2]
        int t2 = (t + 2 <= T_STEPS - 1) ? t + 2 : T_STEPS - 1;
        if (t + 2 <= T_STEPS - 1) wait_chunk(t2);
        const float* p2 = xwp + (size_t)t2 * (BATCH * HID);
        float b0 = p2[0], b1 = p2[32], b2 = p2[64], b3 = p2[96];

        // --- sparse z @ w_rec.T, ascending j (bitwise == dense chain) ---
        float r0 = 0.f, r1 = 0.f, r2 = 0.f, r3 = 0.f, os = 0.f;
#define SPIKES(MM, BASE)                                                        \
        while (MM) {                                                            \
            int b = __ffs(MM) - 1; MM &= MM - 1;                                \
            int j = (BASE) + b;                                                 \
            float4 w = *(const float4*)&wr_p[(j << 7) + (lane << 2)];           \
            r0 = __fadd_rn(r0, w.x); r1 = __fadd_rn(r1, w.y);                   \
            r2 = __fadd_rn(r2, w.z); r3 = __fadd_rn(r3, w.w);                   \
            if (lane < OUT_DIM) os = __fadd_rn(os, wo_s[(j << 4) + lane]);      \
        }
        SPIKES(m0, 0)
        SPIKES(m1, 32)
        SPIKES(m2, 64)
        SPIKES(m3, 96)
#undef SPIKES

        c0 = __fadd_rn(__fadd_rn(id0, x0), r0);
        c1 = __fadd_rn(__fadd_rn(id1, x1), r1);
        c2 = __fadd_rn(__fadd_rn(id2, x2), r2);
        c3 = __fadd_rn(__fadd_rn(id3, x3), r3);

        // --- LI readout (lanes 0..9) ---
        if (lane < OUT_DIM) {
            float ij = __fadd_rn(io, os);
            vo = __fadd_rn(vo, __fmul_rn(0.1f, __fadd_rn(__fsub_rn(0.f, vo), ij)));
            io = __fsub_rn(ij, __fmul_rn(0.2f, ij));
        }

        x0 = a0; x1 = a1; x2 = a2; x3 = a3;
        a0 = b0; a1 = b1; a2 = b2; a3 = b3;
    }

    // --- log_softmax over 10 outputs ---
    float mx = -INFINITY;
#pragma unroll
    for (int o = 0; o < OUT_DIM; ++o)
        mx = fmaxf(mx, __shfl_sync(0xffffffffu, vo, o));
    float s = 0.f;
#pragma unroll
    for (int o = 0; o < OUT_DIM; ++o)
        s = __fadd_rn(s, expf(__fsub_rn(__shfl_sync(0xffffffffu, vo, o), mx)));
    if (lane < OUT_DIM)
        out[batch * OUT_DIM + lane] = __fsub_rn(__fsub_rn(vo, mx), logf(s));
}

// ---------------------------------------------------------------------------
extern "C" void kernel_launch(void* const* d_in, const int* in_sizes, int n_in,
                              void* d_out, int out_size) {
    const float* x     = (const float*)d_in[0];
    const float* w_in  = (const float*)d_in[1];
    const float* w_rec = (const float*)d_in[2];
    const float* w_out = (const float*)d_in[3];
    float* out = (float*)d_out;

    float* xw = nullptr;
    float* w_inT = nullptr;
    cudaGetSymbolAddress((void**)&xw, g_xw);
    cudaGetSymbolAddress((void**)&w_inT, g_w_inT);

    init_kernel<<<40, 256>>>(w_in, w_inT);

    // smem = max(consumer 73728 B, producer 61696 B) = 73728 B
    size_t smem_bytes = (size_t)(HID * HID + HID * 16) * sizeof(float);
    cudaFuncSetAttribute(snn_fused_kernel, cudaFuncAttributeMaxDynamicSharedMemorySize,
                         (int)smem_bytes);
    snn_fused_kernel<<<N_CTAS, 256, smem_bytes>>>(x, w_inT, w_rec, w_out, xw, out);
}

// round 8
// speedup vs baseline: 1.1554x; 1.1554x over previous
#include <cuda_runtime.h>
#include <math.h>

#define T_STEPS 1000
#define BATCH   1024
#define IN_DIM  80
#define HID     128
#define OUT_DIM 10
#define TILE_R  64

typedef unsigned long long ull;

__device__ float g_xw[(size_t)T_STEPS * BATCH * HID];   // 512 MB scratch
__device__ float g_w_inT[IN_DIM * HID];                 // w_inT[k*128+h] = w_in[h*80+k]

__device__ __forceinline__ ull ffma2(ull a, ull b, ull c) {
    ull d; asm("fma.rn.f32x2 %0, %1, %2, %3;" : "=l"(d) : "l"(a), "l"(b), "l"(c)); return d;
}

// ---------------------------------------------------------------------------
// Tiny transpose of w_in (40 KB, one-time per launch)
// ---------------------------------------------------------------------------
__global__ void wtrans_kernel(const float* __restrict__ w_in, float* __restrict__ w_inT) {
    int idx = blockIdx.x * 256 + threadIdx.x;
    if (idx < IN_DIM * HID) {
        int k = idx >> 7, h = idx & 127;
        w_inT[idx] = w_in[h * IN_DIM + k];
    }
}

// ---------------------------------------------------------------------------
// Kernel A: xw[row][h] = ascending-k single-acc fma chain of x[row][k]*w_in[h][k]
// (bitwise identical chain to R4). 42-instr inner loop:
//   x staged PRE-SPLATTED as float2{v,v}  -> 8x LDS.64 (no pk2)
//   w as LDS.128 pairs                    -> 2x LDS.128
//   32x ffma2
// CTA: 128 threads, 64 rows x 128 h; thread = rows rg+8i (i<8) x h {4hg..4hg+3, +64}
// ---------------------------------------------------------------------------
__global__ void __launch_bounds__(128) xw_gemm_kernel(const float* __restrict__ x,
                                                      const float* __restrict__ w_inT,
                                                      float* __restrict__ xw) {
    extern __shared__ float smem_g[];
    float2* xs2 = (float2*)smem_g;                    // [64*80] splat pairs (40 KB)
    float*  ws  = smem_g + 2 * TILE_R * IN_DIM;       // [80][128]           (40 KB)

    long row0 = (long)blockIdx.x * TILE_R;
    int tid = threadIdx.x;

    const float* xsrc = x + row0 * IN_DIM;
    for (int idx = tid; idx < TILE_R * IN_DIM; idx += 128) {
        float v = xsrc[idx];                          // coalesced LDG
        xs2[idx] = make_float2(v, v);                 // STS.64, conflict-free
    }
    for (int idx = tid; idx < IN_DIM * HID; idx += 128)
        ws[idx] = w_inT[idx];                         // coalesced both sides
    __syncthreads();

    int hg = tid & 15;    // h base 4*hg and 64+4*hg
    int rg = tid >> 4;    // rows rg + 8*i

    ull acc[8][4];
#pragma unroll
    for (int i = 0; i < 8; ++i)
#pragma unroll
        for (int j = 0; j < 4; ++j) acc[i][j] = 0ull;

#pragma unroll 10
    for (int k = 0; k < IN_DIM; ++k) {
        ulonglong2 wA = *(const ulonglong2*)&ws[k * HID + 4 * hg];        // LDS.128
        ulonglong2 wB = *(const ulonglong2*)&ws[k * HID + 64 + 4 * hg];   // LDS.128
#pragma unroll
        for (int i = 0; i < 8; ++i) {
            ull xd = *(const ull*)&xs2[(rg + 8 * i) * IN_DIM + k];        // LDS.64 splat
            acc[i][0] = ffma2(xd, wA.x, acc[i][0]);
            acc[i][1] = ffma2(xd, wA.y, acc[i][1]);
            acc[i][2] = ffma2(xd, wB.x, acc[i][2]);
            acc[i][3] = ffma2(xd, wB.y, acc[i][3]);
        }
    }

#pragma unroll
    for (int i = 0; i < 8; ++i) {
        float* dst = &xw[(row0 + rg + 8 * i) * HID];
        ulonglong2 oA; oA.x = acc[i][0]; oA.y = acc[i][1];
        ulonglong2 oB; oB.x = acc[i][2]; oB.y = acc[i][3];
        *(ulonglong2*)&dst[4 * hg]      = oA;         // STG.128, coalesced
        *(ulonglong2*)&dst[64 + 4 * hg] = oB;
    }
}

// ---------------------------------------------------------------------------
// Kernel B: recurrence, warp-per-batch (no barriers, no smem masks).
// Lane l owns h = l, l+32, l+64, l+96. Ballots combined into 2x u64 so the
// ffsll walk visits j strictly ascending (bitwise == dense fma chain).
// wr_p[j][4l+m] permuted so each spike is one conflict-free LDS.128.
// ---------------------------------------------------------------------------
__global__ void __launch_bounds__(256) snn_rec_kernel(const float* __restrict__ xw,
                                                      const float* __restrict__ w_rec,
                                                      const float* __restrict__ w_out,
                                                      float* __restrict__ out) {
    extern __shared__ float smem[];
    float* wr_p = smem;              // [128][128] permuted: wr_p[j*128+4*(h&31)+(h>>5)]
    float* wo_s = smem + HID * HID;  // [128][16]: wo_s[j*16+o] = w_out[o][j]

    int tid = threadIdx.x;
    for (int idx = tid; idx < HID * HID; idx += 256) {
        int h = idx >> 7, j = idx & 127;
        wr_p[(j << 7) + ((h & 31) << 2) + (h >> 5)] = w_rec[idx];   // coalesced LDG
    }
    for (int idx = tid; idx < HID * 16; idx += 256) {
        int j = idx >> 4, o = idx & 15;
        wo_s[idx] = (o < OUT_DIM) ? w_out[o * HID + j] : 0.0f;
    }
    __syncthreads();

    int warp = tid >> 5, lane = tid & 31;
    int batch = blockIdx.x * 8 + warp;

    float v0 = 0.f, v1 = 0.f, v2 = 0.f, v3 = 0.f;
    float c0 = 0.f, c1 = 0.f, c2 = 0.f, c3 = 0.f;
    float vo = 0.f, io = 0.f;        // lanes 0..9: o = lane

    const float* xwp = xw + (size_t)batch * HID + lane;
    float x0 = xwp[0], x1 = xwp[32], x2 = xwp[64], x3 = xwp[96];

    for (int t = 0; t < T_STEPS; ++t) {
        // --- LIF (exact reference expression order, separate rounding) ---
        float vd0 = __fadd_rn(v0, __fmul_rn(0.1f, __fadd_rn(__fsub_rn(0.f, v0), c0)));
        float vd1 = __fadd_rn(v1, __fmul_rn(0.1f, __fadd_rn(__fsub_rn(0.f, v1), c1)));
        float vd2 = __fadd_rn(v2, __fmul_rn(0.1f, __fadd_rn(__fsub_rn(0.f, v2), c2)));
        float vd3 = __fadd_rn(v3, __fmul_rn(0.1f, __fadd_rn(__fsub_rn(0.f, v3), c3)));
        float id0 = __fsub_rn(c0, __fmul_rn(0.2f, c0));
        float id1 = __fsub_rn(c1, __fmul_rn(0.2f, c1));
        float id2 = __fsub_rn(c2, __fmul_rn(0.2f, c2));
        float id3 = __fsub_rn(c3, __fmul_rn(0.2f, c3));
        bool z0 = __fsub_rn(vd0, 1.0f) > 0.0f;
        bool z1 = __fsub_rn(vd1, 1.0f) > 0.0f;
        bool z2 = __fsub_rn(vd2, 1.0f) > 0.0f;
        bool z3 = __fsub_rn(vd3, 1.0f) > 0.0f;
        v0 = z0 ? 0.f : vd0;
        v1 = z1 ? 0.f : vd1;
        v2 = z2 ? 0.f : vd2;
        v3 = z3 ? 0.f : vd3;

        unsigned m0 = __ballot_sync(0xffffffffu, z0);
        unsigned m1 = __ballot_sync(0xffffffffu, z1);
        unsigned m2 = __ballot_sync(0xffffffffu, z2);
        unsigned m3 = __ballot_sync(0xffffffffu, z3);
        ull lo = (ull)m0 | ((ull)m1 << 32);   // j 0..63
        ull hi = (ull)m2 | ((ull)m3 << 32);   // j 64..127

        // prefetch next step's input current
        const float* np = xwp + (size_t)(t < T_STEPS - 1 ? t + 1 : t) * (BATCH * HID);
        float n0 = np[0], n1 = np[32], n2 = np[64], n3 = np[96];

        // --- sparse z @ w_rec.T, ascending j (bitwise == dense chain) ---
        float r0 = 0.f, r1 = 0.f, r2 = 0.f, r3 = 0.f, os = 0.f;
#define SPIKES(MM, BASE)                                                        \
        while (MM) {                                                            \
            int b = __ffsll(MM) - 1; MM &= MM - 1;                              \
            int j = (BASE) + b;                                                 \
            float4 w = *(const float4*)&wr_p[(j << 7) + (lane << 2)];           \
            r0 = __fadd_rn(r0, w.x); r1 = __fadd_rn(r1, w.y);                   \
            r2 = __fadd_rn(r2, w.z); r3 = __fadd_rn(r3, w.w);                   \
            if (lane < OUT_DIM) os = __fadd_rn(os, wo_s[(j << 4) + lane]);      \
        }
        SPIKES(lo, 0)
        SPIKES(hi, 64)
#undef SPIKES

        c0 = __fadd_rn(__fadd_rn(id0, x0), r0);
        c1 = __fadd_rn(__fadd_rn(id1, x1), r1);
        c2 = __fadd_rn(__fadd_rn(id2, x2), r2);
        c3 = __fadd_rn(__fadd_rn(id3, x3), r3);

        // --- LI readout (lanes 0..9, o = lane) ---
        if (lane < OUT_DIM) {
            float ij = __fadd_rn(io, os);
            vo = __fadd_rn(vo, __fmul_rn(0.1f, __fadd_rn(__fsub_rn(0.f, vo), ij)));
            io = __fsub_rn(ij, __fmul_rn(0.2f, ij));
        }

        x0 = n0; x1 = n1; x2 = n2; x3 = n3;
    }

    // --- log_softmax over 10 outputs (ascending-o chains) ---
    float mx = -INFINITY;
#pragma unroll
    for (int o = 0; o < OUT_DIM; ++o)
        mx = fmaxf(mx, __shfl_sync(0xffffffffu, vo, o));
    float s = 0.f;
#pragma unroll
    for (int o = 0; o < OUT_DIM; ++o)
        s = __fadd_rn(s, expf(__fsub_rn(__shfl_sync(0xffffffffu, vo, o), mx)));
    if (lane < OUT_DIM)
        out[batch * OUT_DIM + lane] = __fsub_rn(__fsub_rn(vo, mx), logf(s));
}

// ---------------------------------------------------------------------------
extern "C" void kernel_launch(void* const* d_in, const int* in_sizes, int n_in,
                              void* d_out, int out_size) {
    const float* x     = (const float*)d_in[0];
    const float* w_in  = (const float*)d_in[1];
    const float* w_rec = (const float*)d_in[2];
    const float* w_out = (const float*)d_in[3];
    float* out = (float*)d_out;

    float* xw = nullptr;
    float* w_inT = nullptr;
    cudaGetSymbolAddress((void**)&xw, g_xw);
    cudaGetSymbolAddress((void**)&w_inT, g_w_inT);

    wtrans_kernel<<<(IN_DIM * HID + 255) / 256, 256>>>(w_in, w_inT);

    // GEMM smem: 40KB x-splat + 40KB w = 80KB -> 2 CTAs/SM
    size_t gemm_smem = (size_t)(2 * TILE_R * IN_DIM + IN_DIM * HID) * sizeof(float);
    cudaFuncSetAttribute(xw_gemm_kernel, cudaFuncAttributeMaxDynamicSharedMemorySize,
                         (int)gemm_smem);
    xw_gemm_kernel<<<(T_STEPS * BATCH) / TILE_R, 128, gemm_smem>>>(x, w_inT, xw);

    size_t rec_smem = (size_t)(HID * HID + HID * 16) * sizeof(float);
    cudaFuncSetAttribute(snn_rec_kernel, cudaFuncAttributeMaxDynamicSharedMemorySize,
                         (int)rec_smem);
    snn_rec_kernel<<<128, 256, rec_smem>>>(xw, w_rec, w_out, out);
}

// round 9
// speedup vs baseline: 1.2510x; 1.0828x over previous
#include <cuda_runtime.h>
#include <math.h>

#define T_STEPS 1000
#define BATCH   1024
#define IN_DIM  80
#define HID     128
#define OUT_DIM 10

#define GTILE    32                              // rows per GEMM tile
#define N_GTILES ((T_STEPS * BATCH) / GTILE)     // 32000
#define N_GCTAS  444                             // 148 SMs * 3, persistent

typedef unsigned long long ull;

__device__ float g_xw[(size_t)T_STEPS * BATCH * HID];   // 512 MB scratch
__device__ float g_w_inT[IN_DIM * HID];                 // w_inT[k*128+h] = w_in[h*80+k]

__device__ __forceinline__ ull ffma2(ull a, ull b, ull c) {
    ull d; asm("fma.rn.f32x2 %0, %1, %2, %3;" : "=l"(d) : "l"(a), "l"(b), "l"(c)); return d;
}

// ---------------------------------------------------------------------------
// Tiny transpose of w_in (40 KB, once per launch)
// ---------------------------------------------------------------------------
__global__ void wtrans_kernel(const float* __restrict__ w_in, float* __restrict__ w_inT) {
    int idx = blockIdx.x * 256 + threadIdx.x;
    if (idx < IN_DIM * HID) {
        int k = idx >> 7, h = idx & 127;
        w_inT[idx] = w_in[h * IN_DIM + k];
    }
}

// ---------------------------------------------------------------------------
// Kernel A (persistent): xw[row][h] = ascending-k single-acc fma chain.
// w staged in smem ONCE per CTA; loop over 32-row tiles (blockIdx-strided).
// Inner loop/k: 2x LDS.128 (w pairs) + 4x LDS.64 (splatted x) + 16 ffma2.
// Thread (hg=tid&15, rg=tid>>4): rows rg+8i (i<4), h in {4hg..4hg+3, 64+4hg..}.
// Bitwise chain identical to R4 (per-lane fma.rn, ascending k, single acc).
// ---------------------------------------------------------------------------
__global__ void __launch_bounds__(128) xw_gemm_kernel(const float* __restrict__ x,
                                                      const float* __restrict__ w_inT,
                                                      float* __restrict__ xw) {
    extern __shared__ float smg[];
    float2* xs2 = (float2*)smg;                   // [32*80] splat pairs (20 KB)
    float*  ws  = smg + 2 * GTILE * IN_DIM;       // [80][128]           (40 KB)

    int tid = threadIdx.x;
    for (int idx = tid; idx < IN_DIM * HID; idx += 128)
        ws[idx] = w_inT[idx];                     // staged once, coalesced

    int hg = tid & 15;
    int rg = tid >> 4;

    for (int tile = blockIdx.x; tile < N_GTILES; tile += N_GCTAS) {
        long row0 = (long)tile * GTILE;
        __syncthreads();                          // xs2 free (also orders ws on iter 0)
        const float* xsrc = x + row0 * IN_DIM;
        for (int idx = tid; idx < GTILE * IN_DIM; idx += 128) {
            float v = xsrc[idx];                  // coalesced LDG
            xs2[idx] = make_float2(v, v);         // STS.64 splat
        }
        __syncthreads();

        ull acc[4][4];
#pragma unroll
        for (int i = 0; i < 4; ++i)
#pragma unroll
            for (int j = 0; j < 4; ++j) acc[i][j] = 0ull;

#pragma unroll 10
        for (int k = 0; k < IN_DIM; ++k) {
            ulonglong2 wA = *(const ulonglong2*)&ws[k * HID + 4 * hg];        // LDS.128
            ulonglong2 wB = *(const ulonglong2*)&ws[k * HID + 64 + 4 * hg];   // LDS.128
#pragma unroll
            for (int i = 0; i < 4; ++i) {
                ull xd = *(const ull*)&xs2[(rg + 8 * i) * IN_DIM + k];        // LDS.64
                acc[i][0] = ffma2(xd, wA.x, acc[i][0]);
                acc[i][1] = ffma2(xd, wA.y, acc[i][1]);
                acc[i][2] = ffma2(xd, wB.x, acc[i][2]);
                acc[i][3] = ffma2(xd, wB.y, acc[i][3]);
            }
        }

#pragma unroll
        for (int i = 0; i < 4; ++i) {
            float* dst = &xw[(row0 + rg + 8 * i) * HID];
            ulonglong2 oA; oA.x = acc[i][0]; oA.y = acc[i][1];
            ulonglong2 oB; oB.x = acc[i][2]; oB.y = acc[i][3];
            *(ulonglong2*)&dst[4 * hg]      = oA;     // STG.128 coalesced
            *(ulonglong2*)&dst[64 + 4 * hg] = oB;
        }
    }
}

// ---------------------------------------------------------------------------
// Kernel B: recurrence — R4 verbatim (proven). Warp-per-batch, no barriers.
// Lane l owns h = l, l+32, l+64, l+96; ballots give ascending-j spike walk
// (bitwise == dense fma chain). wr_p permuted for conflict-free LDS.128.
// ---------------------------------------------------------------------------
__global__ void __launch_bounds__(256) snn_rec_kernel(const float* __restrict__ xw,
                                                      const float* __restrict__ w_rec,
                                                      const float* __restrict__ w_out,
                                                      float* __restrict__ out) {
    extern __shared__ float smem[];
    float* wr_p = smem;              // [128][128] permuted: wr_p[j*128+4*(h&31)+(h>>5)]
    float* wo_s = smem + HID * HID;  // [128][16]: wo_s[j*16+o] = w_out[o][j]

    int tid = threadIdx.x;
    for (int idx = tid; idx < HID * HID; idx += 256) {
        int h = idx >> 7, j = idx & 127;
        wr_p[(j << 7) + ((h & 31) << 2) + (h >> 5)] = w_rec[idx];
    }
    for (int idx = tid; idx < HID * 16; idx += 256) {
        int j = idx >> 4, o = idx & 15;
        wo_s[idx] = (o < OUT_DIM) ? w_out[o * HID + j] : 0.0f;
    }
    __syncthreads();

    int warp = tid >> 5, lane = tid & 31;
    int batch = blockIdx.x * 8 + warp;

    float v0 = 0.f, v1 = 0.f, v2 = 0.f, v3 = 0.f;
    float c0 = 0.f, c1 = 0.f, c2 = 0.f, c3 = 0.f;
    float vo = 0.f, io = 0.f;

    const float* xwp = xw + (size_t)batch * HID + lane;
    float x0 = xwp[0], x1 = xwp[32], x2 = xwp[64], x3 = xwp[96];

    for (int t = 0; t < T_STEPS; ++t) {
        float vd0 = __fadd_rn(v0, __fmul_rn(0.1f, __fadd_rn(__fsub_rn(0.f, v0), c0)));
        float vd1 = __fadd_rn(v1, __fmul_rn(0.1f, __fadd_rn(__fsub_rn(0.f, v1), c1)));
        float vd2 = __fadd_rn(v2, __fmul_rn(0.1f, __fadd_rn(__fsub_rn(0.f, v2), c2)));
        float vd3 = __fadd_rn(v3, __fmul_rn(0.1f, __fadd_rn(__fsub_rn(0.f, v3), c3)));
        float id0 = __fsub_rn(c0, __fmul_rn(0.2f, c0));
        float id1 = __fsub_rn(c1, __fmul_rn(0.2f, c1));
        float id2 = __fsub_rn(c2, __fmul_rn(0.2f, c2));
        float id3 = __fsub_rn(c3, __fmul_rn(0.2f, c3));
        bool z0 = __fsub_rn(vd0, 1.0f) > 0.0f;
        bool z1 = __fsub_rn(vd1, 1.0f) > 0.0f;
        bool z2 = __fsub_rn(vd2, 1.0f) > 0.0f;
        bool z3 = __fsub_rn(vd3, 1.0f) > 0.0f;
        v0 = z0 ? 0.f : vd0;
        v1 = z1 ? 0.f : vd1;
        v2 = z2 ? 0.f : vd2;
        v3 = z3 ? 0.f : vd3;

        unsigned m0 = __ballot_sync(0xffffffffu, z0);
        unsigned m1 = __ballot_sync(0xffffffffu, z1);
        unsigned m2 = __ballot_sync(0xffffffffu, z2);
        unsigned m3 = __ballot_sync(0xffffffffu, z3);

        const float* np = xwp + (size_t)(t < T_STEPS - 1 ? t + 1 : t) * (BATCH * HID);
        float n0 = np[0], n1 = np[32], n2 = np[64], n3 = np[96];

        float r0 = 0.f, r1 = 0.f, r2 = 0.f, r3 = 0.f, os = 0.f;
#define SPIKES(MM, BASE)                                                        \
        while (MM) {                                                            \
            int b = __ffs(MM) - 1; MM &= MM - 1;                                \
            int j = (BASE) + b;                                                 \
            float4 w = *(const float4*)&wr_p[(j << 7) + (lane << 2)];           \
            r0 = __fadd_rn(r0, w.x); r1 = __fadd_rn(r1, w.y);                   \
            r2 = __fadd_rn(r2, w.z); r3 = __fadd_rn(r3, w.w);                   \
            if (lane < OUT_DIM) os = __fadd_rn(os, wo_s[(j << 4) + lane]);      \
        }
        SPIKES(m0, 0)
        SPIKES(m1, 32)
        SPIKES(m2, 64)
        SPIKES(m3, 96)
#undef SPIKES

        c0 = __fadd_rn(__fadd_rn(id0, x0), r0);
        c1 = __fadd_rn(__fadd_rn(id1, x1), r1);
        c2 = __fadd_rn(__fadd_rn(id2, x2), r2);
        c3 = __fadd_rn(__fadd_rn(id3, x3), r3);

        if (lane < OUT_DIM) {
            float ij = __fadd_rn(io, os);
            vo = __fadd_rn(vo, __fmul_rn(0.1f, __fadd_rn(__fsub_rn(0.f, vo), ij)));
            io = __fsub_rn(ij, __fmul_rn(0.2f, ij));
        }

        x0 = n0; x1 = n1; x2 = n2; x3 = n3;
    }

    float mx = -INFINITY;
#pragma unroll
    for (int o = 0; o < OUT_DIM; ++o)
        mx = fmaxf(mx, __shfl_sync(0xffffffffu, vo, o));
    float s = 0.f;
#pragma unroll
    for (int o = 0; o < OUT_DIM; ++o)
        s = __fadd_rn(s, expf(__fsub_rn(__shfl_sync(0xffffffffu, vo, o), mx)));
    if (lane < OUT_DIM)
        out[batch * OUT_DIM + lane] = __fsub_rn(__fsub_rn(vo, mx), logf(s));
}

// ---------------------------------------------------------------------------
extern "C" void kernel_launch(void* const* d_in, const int* in_sizes, int n_in,
                              void* d_out, int out_size) {
    const float* x     = (const float*)d_in[0];
    const float* w_in  = (const float*)d_in[1];
    const float* w_rec = (const float*)d_in[2];
    const float* w_out = (const float*)d_in[3];
    float* out = (float*)d_out;

    float* xw = nullptr;
    float* w_inT = nullptr;
    cudaGetSymbolAddress((void**)&xw, g_xw);
    cudaGetSymbolAddress((void**)&w_inT, g_w_inT);

    wtrans_kernel<<<(IN_DIM * HID + 255) / 256, 256>>>(w_in, w_inT);

    // GEMM smem: 20KB x-splat + 40KB w = 60KB -> 3 CTAs/SM (persistent grid)
    size_t gemm_smem = (size_t)(2 * GTILE * IN_DIM + IN_DIM * HID) * sizeof(float);
    cudaFuncSetAttribute(xw_gemm_kernel, cudaFuncAttributeMaxDynamicSharedMemorySize,
                         (int)gemm_smem);
    xw_gemm_kernel<<<N_GCTAS, 128, gemm_smem>>>(x, w_inT, xw);

    size_t rec_smem = (size_t)(HID * HID + HID * 16) * sizeof(float);
    cudaFuncSetAttribute(snn_rec_kernel, cudaFuncAttributeMaxDynamicSharedMemorySize,
                         (int)rec_smem);
    snn_rec_kernel<<<128, 256, rec_smem>>>(xw, w_rec, w_out, out);
}